// round 11
// baseline (speedup 1.0000x reference)
#include <cuda_runtime.h>
#include <cuda_fp16.h>
#include <cstdint>

// ---------------------------------------------------------------------------
// Fused two-tower scorer, round 11: KC=64 (two stacked 16-uint planes per
// chunk, R9-verified conflict-free LDS.128 pattern per plane), NCHUNK=16 ->
// half the barriers and per-chunk overhead of R10. 2 CTAs/SM kept (TB=64,
// 512 thr, launch_bounds(512,2)); user latent round-trips through an 8 MB
// __device__ scratch instead of smem so W stays double-buffered in 83 KB.
// ---------------------------------------------------------------------------

#define NTHREADS 512
#define TB       64      // batch rows per CTA
#define LOUT     256     // latents (GEMM N)
#define KF       512     // features (GEMM K)
#define KC       64      // K chunk (elements) = 2 planes of 16 fp16-pairs/row
#define NCHUNK   16      // 8 chunks per tower x 2 towers
#define PLA      1024    // A plane stride (uints) = 64 rows x 16
#define PLW      4096    // W plane stride (uints) = 256 rows x 16

// smem byte offsets
#define S_IDXU   0                       // 64 ints
#define S_IDXI   256
#define S_UB     512                     // 256 f32
#define S_IB     1536
#define S_PART   2560                    // 64 f32
#define S_A      4096                    // A tiles: 2 planes, double buffered
#define A_BYTES  (2 * PLA * 4)           // 8192
#define S_W      (S_A + 2 * A_BYTES)     // 20480, W: 2 planes, double buffered
#define W_BYTES  (2 * PLW * 4)           // 32768
#define S_TOTAL  (S_W + 2 * W_BYTES)     // 86016 -> 2 CTAs/SM

// pre-converted, permuted fp16 weights:
// index = tower*65536 + ch*8192 + h*4096 + l*16 + pos
// pos = 4t + 2s + b  for local pair q = 8s + 4b + t  (k = ch*64 + h*32 + 2q)
__device__ uint32_t wscr[2 * 8 * 2 * LOUT * 16];

// user-latent scratch: [16384 rows][128 half2]
__device__ __half2 ulat_g[16384 * 128];

// --------------------------- helpers ----------------------------------------

__device__ __forceinline__ void mma16(float* c, uint32_t a0, uint32_t a1,
                                      uint32_t a2, uint32_t a3,
                                      uint32_t b0, uint32_t b1) {
    asm volatile(
        "mma.sync.aligned.m16n8k16.row.col.f32.f16.f16.f32 "
        "{%0,%1,%2,%3}, {%4,%5,%6,%7}, {%8,%9}, {%0,%1,%2,%3};"
        : "+f"(c[0]), "+f"(c[1]), "+f"(c[2]), "+f"(c[3])
        : "r"(a0), "r"(a1), "r"(a2), "r"(a3), "r"(b0), "r"(b1));
}

__device__ __forceinline__ void cp16(uint32_t dst, const void* src) {
    asm volatile("cp.async.cg.shared.global [%0], [%1], 16;"
                 :: "r"(dst), "l"(src) : "memory");
}

__device__ __forceinline__ uint32_t h2u(__half2 h) {
    return *reinterpret_cast<uint32_t*>(&h);
}

// pos(q) = 4*(q&3) + 2*(q>>3) + ((q>>2)&1)   (within one 16-pair plane)
__device__ __forceinline__ int posof(int q) {
    return ((q & 3) << 2) | ((q >> 3) << 1) | ((q >> 2) & 1);
}

// W chunk c (2 planes) -> smem buffer c&1
__device__ __forceinline__ void issue_w(int c, uint32_t sb, int tid) {
    const int tower = c >> 3, ch = c & 7, buf = c & 1;
    const uint32_t* src0 = wscr + tower * 65536 + ch * 8192;
    const uint32_t dst0 = sb + S_W + buf * W_BYTES;
    // 2048 16B segs / 512 thr = 4 per thread (src is contiguous)
#pragma unroll
    for (int i = 0; i < 4; i++) {
        int seg = tid + i * NTHREADS;
        cp16(dst0 + seg * 16, src0 + seg * 4);
    }
    asm volatile("cp.async.commit_group;" ::: "memory");
}

// A chunk: 64 rows x 16 float4 = 1024 segs / 512 thr = 2 per thread
__device__ __forceinline__ void ldg_a(float4* pref, const float* lut,
                                      const int* idx, int kc, int tid) {
#pragma unroll
    for (int i = 0; i < 2; i++) {
        int seg = tid + i * NTHREADS;
        int row = seg >> 4, q = seg & 15;
        pref[i] = __ldg(reinterpret_cast<const float4*>(
            lut + (size_t)idx[row] * KF + kc + q * 4));
    }
}

// store A chunk as fp16 pairs: seg q: plane h=q>>3, local pairs 2(q&7), +1
__device__ __forceinline__ void sts_a(const float4* pref, char* smem, int c,
                                      int tid) {
    uint32_t* base = (uint32_t*)(smem + S_A + (c & 1) * A_BYTES);
#pragma unroll
    for (int i = 0; i < 2; i++) {
        int seg = tid + i * NTHREADS;
        int row = seg >> 4, q = seg & 15;
        int h = q >> 3, qq = q & 7;
        uint32_t* rp = base + h * PLA + row * 16;
        rp[posof(2 * qq)]     = h2u(__floats2half2_rn(pref[i].x, pref[i].y));
        rp[posof(2 * qq + 1)] = h2u(__floats2half2_rn(pref[i].z, pref[i].w));
    }
}

// --------------------------- prep kernel ------------------------------------

__global__ void prep_kernel(const float* __restrict__ uW,
                            const float* __restrict__ iW) {
    int o = blockIdx.x * 256 + threadIdx.x;        // [0, 131072)
    int tower = o >> 16;
    int r = o & 65535;
    int ch = r >> 13;
    int h  = (r >> 12) & 1;
    int l  = (r >> 4) & (LOUT - 1);
    int pos = r & 15;
    int t = pos >> 2, s = (pos >> 1) & 1, b = pos & 1;
    int q = 8 * s + 4 * b + t;
    const float* W = (tower ? iW : uW) + (size_t)l * KF + ch * KC + h * 32
                     + 2 * q;
    wscr[o] = h2u(__floats2half2_rn(W[0], W[1]));
}

// --------------------------- main kernel ------------------------------------

__global__ void __launch_bounds__(NTHREADS, 2) towers_kernel(
    const int* __restrict__ x,
    const float* __restrict__ ulut, const float* __restrict__ ilut,
    const float* __restrict__ ubias, const float* __restrict__ ibias,
    float* __restrict__ out) {
    extern __shared__ char smem[];
    uint32_t sb;
    asm("{ .reg .u64 t; cvta.to.shared.u64 t, %1; cvt.u32.u64 %0, t; }"
        : "=r"(sb) : "l"(smem));
    const int tid  = threadIdx.x;
    const int lane = tid & 31;
    const int wid  = tid >> 5;
    const int wm   = wid & 3;        // 4 row groups of 16
    const int wn   = wid >> 2;       // 4 col groups of 64
    const int g    = lane >> 2;
    const int t    = lane & 3;

    int*   idxu = (int*)(smem + S_IDXU);
    int*   idxi = (int*)(smem + S_IDXI);
    float* ubS  = (float*)(smem + S_UB);
    float* ibS  = (float*)(smem + S_IB);
    float* part = (float*)(smem + S_PART);

    if (tid < LOUT) {
        ubS[tid] = ubias[tid];
        ibS[tid] = ibias[tid];
    }
    if (tid < TB) {
        part[tid] = 0.f;
        int gg = blockIdx.x * TB + tid;
        idxu[tid] = x[2 * gg];
        idxi[tid] = x[2 * gg + 1];
    }
    __syncthreads();

    issue_w(0, sb, tid);

    float4 pref[2];
    ldg_a(pref, ulut, idxu, 0, tid);

    float acc[8][4];
#pragma unroll
    for (int nt = 0; nt < 8; nt++)
#pragma unroll
        for (int i = 0; i < 4; i++) acc[nt][i] = 0.f;

    const int rlo = wm * 16 + g;         // fragment rows within tile
    const int rhi = wm * 16 + 8 + g;
    const int glo = blockIdx.x * TB + rlo;   // global rows
    const int ghi = blockIdx.x * TB + rhi;

    for (int c = 0; c < NCHUNK; c++) {
        // 1. store prefetched A; buffer (c&1)'s last reader MMA(c-2) is
        //    CTA-wide complete past sync(c-1).
        sts_a(pref, smem, c, tid);

        // 2. prefetch next A chunk
        if (c + 1 < NCHUNK) {
            int c2 = c + 1;
            bool t2 = (c2 >= NCHUNK / 2);
            ldg_a(pref, t2 ? ilut : ulut, t2 ? idxi : idxu,
                  (c2 & 7) * KC, tid);
        }

        // 3. W chunk c arrived (only group c outstanding here)
        asm volatile("cp.async.wait_group 0;" ::: "memory");
        __syncthreads();

        // 4. refill W buffer (c+1)&1: its last reader MMA(c-1) done pre-sync
        if (c + 1 < NCHUNK) issue_w(c + 1, sb, tid);

        // 5. MMA on chunk c: 2 planes x 2 k-steps
        const uint32_t* A  = (const uint32_t*)(smem + S_A + (c & 1) * A_BYTES);
        const uint32_t* Bs = (const uint32_t*)(smem + S_W + (c & 1) * W_BYTES);
#pragma unroll
        for (int h = 0; h < 2; h++) {
            const uint32_t* Ah = A + h * PLA;
            const uint32_t* Bh = Bs + h * PLW;
            uint4 alo = *(const uint4*)(Ah + rlo * 16 + 4 * t);
            uint4 ahi = *(const uint4*)(Ah + rhi * 16 + 4 * t);
#pragma unroll
            for (int ntb = 0; ntb < 4; ntb++) {      // 2 n-tiles at a time
                const int n0 = wn * 64 + (ntb * 2) * 8 + g;
                uint4 bv0 = *(const uint4*)(Bh + n0 * 16 + 4 * t);
                uint4 bv1 = *(const uint4*)(Bh + (n0 + 8) * 16 + 4 * t);
                // kstep 0: x,y ; kstep 1: z,w
                mma16(acc[ntb * 2],     alo.x, ahi.x, alo.y, ahi.y,
                      bv0.x, bv0.y);
                mma16(acc[ntb * 2 + 1], alo.x, ahi.x, alo.y, ahi.y,
                      bv1.x, bv1.y);
                mma16(acc[ntb * 2],     alo.z, ahi.z, alo.w, ahi.w,
                      bv0.z, bv0.w);
                mma16(acc[ntb * 2 + 1], alo.z, ahi.z, alo.w, ahi.w,
                      bv1.z, bv1.w);
            }
        }

        // 6. user-tower epilogue: bias + relu -> fp16 global scratch
        if (c == NCHUNK / 2 - 1) {
#pragma unroll
            for (int nt = 0; nt < 8; nt++) {
                const int c0 = wn * 64 + nt * 8 + 2 * t;
                float u0 = fmaxf(acc[nt][0] + ubS[c0],     0.f);
                float u1 = fmaxf(acc[nt][1] + ubS[c0 + 1], 0.f);
                float u2 = fmaxf(acc[nt][2] + ubS[c0],     0.f);
                float u3 = fmaxf(acc[nt][3] + ubS[c0 + 1], 0.f);
                const int cc = wn * 32 + nt * 4 + t;     // half2 column
                ulat_g[glo * 128 + cc] = __floats2half2_rn(u0, u1);
                ulat_g[ghi * 128 + cc] = __floats2half2_rn(u2, u3);
                acc[nt][0] = acc[nt][1] = acc[nt][2] = acc[nt][3] = 0.f;
            }
        }
    }

    // item-tower epilogue: bias+relu, product with user latent, row-reduce
    {
        float s0 = 0.f, s1 = 0.f;
#pragma unroll
        for (int nt = 0; nt < 8; nt++) {
            const int c0 = wn * 64 + nt * 8 + 2 * t;
            float v0 = fmaxf(acc[nt][0] + ibS[c0],     0.f);
            float v1 = fmaxf(acc[nt][1] + ibS[c0 + 1], 0.f);
            float v2 = fmaxf(acc[nt][2] + ibS[c0],     0.f);
            float v3 = fmaxf(acc[nt][3] + ibS[c0 + 1], 0.f);
            const int cc = wn * 32 + nt * 4 + t;
            float2 u01 = __half22float2(ulat_g[glo * 128 + cc]);
            float2 u23 = __half22float2(ulat_g[ghi * 128 + cc]);
            s0 = fmaf(u01.x, v0, fmaf(u01.y, v1, s0));
            s1 = fmaf(u23.x, v2, fmaf(u23.y, v3, s1));
        }
        s0 += __shfl_xor_sync(0xffffffffu, s0, 1);
        s0 += __shfl_xor_sync(0xffffffffu, s0, 2);
        s1 += __shfl_xor_sync(0xffffffffu, s1, 1);
        s1 += __shfl_xor_sync(0xffffffffu, s1, 2);
        if (t == 0) {
            atomicAdd(&part[rlo], s0);
            atomicAdd(&part[rhi], s1);
        }
    }
    __syncthreads();

    if (tid < TB) out[blockIdx.x * TB + tid] = part[tid];
}

// --------------------------- launch -----------------------------------------

extern "C" void kernel_launch(void* const* d_in, const int* in_sizes, int n_in,
                              void* d_out, int out_size) {
    const int* x      = (const int*)d_in[0];
    const float* ulut = (const float*)d_in[1];
    const float* ilut = (const float*)d_in[2];
    const float* uW   = (const float*)d_in[3];
    const float* ub   = (const float*)d_in[4];
    const float* iW   = (const float*)d_in[5];
    const float* ib   = (const float*)d_in[6];
    float* out        = (float*)d_out;

    prep_kernel<<<2 * 8 * 2 * LOUT * 16 / 256, 256>>>(uW, iW);

    cudaFuncSetAttribute(towers_kernel,
                         cudaFuncAttributeMaxDynamicSharedMemorySize, S_TOTAL);
    int grid = out_size / TB;   // 16384 / 64 = 256
    towers_kernel<<<grid, NTHREADS, S_TOTAL>>>(x, ulut, ilut, ub, ib, out);
}

// round 14
// speedup vs baseline: 1.0361x; 1.0361x over previous
#include <cuda_runtime.h>
#include <cuda_fp16.h>
#include <cstdint>

// ---------------------------------------------------------------------------
// Fused two-tower scorer, round 13: R12 design with the K-coverage bug fixed.
// NSUPER=16 super-chunks of 64 K (8 per tower, full KF=512). W staged as
// 16KB half-chunks (32 global, 16/tower) in 4 smem buffers, one commit group
// each, incremental wait_group 1 inside the MMA section (~2 transfers always
// in flight). TB=64, 512 thr, 2 CTAs/SM, fp16 m16n8k16, ulat in gmem scratch.
// ---------------------------------------------------------------------------

#define NTHREADS 512
#define TB       64      // batch rows per CTA
#define LOUT     256     // latents (GEMM N)
#define KF       512     // features (GEMM K)
#define NSUPER   16      // super-chunks of 64 K (8 per tower x 2 towers)
#define PLA      1024    // A plane stride (uints) = 64 rows x 16
#define PLW      4096    // W half-chunk size (uints) = 256 rows x 16

// smem byte offsets
#define S_IDXU   0                       // 64 ints
#define S_IDXI   256
#define S_UB     512                     // 256 f32
#define S_IB     1536
#define S_PART   2560                    // 64 f32
#define S_A      4096                    // A: 2 super-buffers x 2 planes
#define A_BYTES  (2 * PLA * 4)           // 8192 per super-buffer
#define S_W      (S_A + 2 * A_BYTES)     // 20480; W: 4 x 16KB half-chunk bufs
#define WH_BYTES (PLW * 4)               // 16384
#define S_TOTAL  (S_W + 4 * WH_BYTES)    // 86016 -> 2 CTAs/SM

// pre-converted, permuted fp16 weights, per-half-chunk contiguous:
// index = tower*65536 + lc*4096 + l*16 + pos   (lc = local half-chunk 0..15)
// pos = 4t + 2s + b for pair q = 8s + 4b + t   (k = lc*32 + 2q, 2q+1)
__device__ uint32_t wscr[2 * 16 * LOUT * 16];    // 131072

// user-latent scratch: [16384 rows][128 half2]
__device__ __half2 ulat_g[16384 * 128];

// --------------------------- helpers ----------------------------------------

__device__ __forceinline__ void mma16(float* c, uint32_t a0, uint32_t a1,
                                      uint32_t a2, uint32_t a3,
                                      uint32_t b0, uint32_t b1) {
    asm volatile(
        "mma.sync.aligned.m16n8k16.row.col.f32.f16.f16.f32 "
        "{%0,%1,%2,%3}, {%4,%5,%6,%7}, {%8,%9}, {%0,%1,%2,%3};"
        : "+f"(c[0]), "+f"(c[1]), "+f"(c[2]), "+f"(c[3])
        : "r"(a0), "r"(a1), "r"(a2), "r"(a3), "r"(b0), "r"(b1));
}

__device__ __forceinline__ void cp16(uint32_t dst, const void* src) {
    asm volatile("cp.async.cg.shared.global [%0], [%1], 16;"
                 :: "r"(dst), "l"(src) : "memory");
}

__device__ __forceinline__ uint32_t h2u(__half2 h) {
    return *reinterpret_cast<uint32_t*>(&h);
}

// pos(q) = 4*(q&3) + 2*(q>>3) + ((q>>2)&1)   (within one 16-pair plane)
__device__ __forceinline__ int posof(int q) {
    return ((q & 3) << 2) | ((q >> 3) << 1) | ((q >> 2) & 1);
}

// W half-chunk hc (0..31 global) -> smem buffer hc&3; own commit group
__device__ __forceinline__ void issue_w(int hc, uint32_t sb, int tid) {
    const uint32_t* src0 = wscr + (hc >> 4) * 65536 + (hc & 15) * 4096;
    const uint32_t dst0 = sb + S_W + (hc & 3) * WH_BYTES;
    // 1024 16B segs / 512 thr = 2 per thread (contiguous)
#pragma unroll
    for (int i = 0; i < 2; i++) {
        int seg = tid + i * NTHREADS;
        cp16(dst0 + seg * 16, src0 + seg * 4);
    }
    asm volatile("cp.async.commit_group;" ::: "memory");
}

// A super-chunk: 64 rows x 16 float4 = 1024 segs / 512 thr = 2 per thread
__device__ __forceinline__ void ldg_a(float4* pref, const float* lut,
                                      const int* idx, int kc, int tid) {
#pragma unroll
    for (int i = 0; i < 2; i++) {
        int seg = tid + i * NTHREADS;
        int row = seg >> 4, q = seg & 15;
        pref[i] = __ldg(reinterpret_cast<const float4*>(
            lut + (size_t)idx[row] * KF + kc + q * 4));
    }
}

// store A super-chunk as fp16 pairs: seg q: plane h=q>>3, local pairs 2(q&7)
__device__ __forceinline__ void sts_a(const float4* pref, char* smem, int s,
                                      int tid) {
    uint32_t* base = (uint32_t*)(smem + S_A + (s & 1) * A_BYTES);
#pragma unroll
    for (int i = 0; i < 2; i++) {
        int seg = tid + i * NTHREADS;
        int row = seg >> 4, q = seg & 15;
        int h = q >> 3, qq = q & 7;
        uint32_t* rp = base + h * PLA + row * 16;
        rp[posof(2 * qq)]     = h2u(__floats2half2_rn(pref[i].x, pref[i].y));
        rp[posof(2 * qq + 1)] = h2u(__floats2half2_rn(pref[i].z, pref[i].w));
    }
}

// --------------------------- prep kernel ------------------------------------

__global__ void prep_kernel(const float* __restrict__ uW,
                            const float* __restrict__ iW) {
    int o = blockIdx.x * 256 + threadIdx.x;        // [0, 131072)
    int tower = o >> 16;                           // 0..1
    int r = o & 65535;
    int lc = r >> 12;                              // local half-chunk 0..15
    int l  = (r >> 4) & (LOUT - 1);
    int pos = r & 15;
    int t = pos >> 2, s = (pos >> 1) & 1, b = pos & 1;
    int q = 8 * s + 4 * b + t;
    const float* W = (tower ? iW : uW) + (size_t)l * KF + lc * 32 + 2 * q;
    wscr[o] = h2u(__floats2half2_rn(W[0], W[1]));
}

// --------------------------- main kernel ------------------------------------

__global__ void __launch_bounds__(NTHREADS, 2) towers_kernel(
    const int* __restrict__ x,
    const float* __restrict__ ulut, const float* __restrict__ ilut,
    const float* __restrict__ ubias, const float* __restrict__ ibias,
    float* __restrict__ out) {
    extern __shared__ char smem[];
    uint32_t sb;
    asm("{ .reg .u64 t; cvta.to.shared.u64 t, %1; cvt.u32.u64 %0, t; }"
        : "=r"(sb) : "l"(smem));
    const int tid  = threadIdx.x;
    const int lane = tid & 31;
    const int wid  = tid >> 5;
    const int wm   = wid & 3;        // 4 row groups of 16
    const int wn   = wid >> 2;       // 4 col groups of 64
    const int g    = lane >> 2;
    const int t    = lane & 3;

    int*   idxu = (int*)(smem + S_IDXU);
    int*   idxi = (int*)(smem + S_IDXI);
    float* ubS  = (float*)(smem + S_UB);
    float* ibS  = (float*)(smem + S_IB);
    float* part = (float*)(smem + S_PART);

    if (tid < LOUT) {
        ubS[tid] = ubias[tid];
        ibS[tid] = ibias[tid];
    }
    if (tid < TB) {
        part[tid] = 0.f;
        int gg = blockIdx.x * TB + tid;
        idxu[tid] = x[2 * gg];
        idxi[tid] = x[2 * gg + 1];
    }
    __syncthreads();

    issue_w(0, sb, tid);
    issue_w(1, sb, tid);

    float4 pref[2];
    ldg_a(pref, ulut, idxu, 0, tid);

    float acc[8][4];
#pragma unroll
    for (int nt = 0; nt < 8; nt++)
#pragma unroll
        for (int i = 0; i < 4; i++) acc[nt][i] = 0.f;

    const int rlo = wm * 16 + g;             // fragment rows within tile
    const int rhi = wm * 16 + 8 + g;
    const int glo = blockIdx.x * TB + rlo;   // global rows
    const int ghi = blockIdx.x * TB + rhi;

    for (int s = 0; s < NSUPER; s++) {
        // 1. store prefetched A super-chunk (buffer s&1); its previous
        //    readers (MMA(s-2)) completed before barrier(s-1).
        sts_a(pref, smem, s, tid);

        // 2. prefetch next A super-chunk
        if (s + 1 < NSUPER) {
            int s2 = s + 1;
            bool t2 = (s2 >= NSUPER / 2);
            ldg_a(pref, t2 ? ilut : ulut, t2 ? idxi : idxu,
                  (s2 & 7) * 64, tid);
        }

        // 3. W half-chunk 2s ready (2s+1 still in flight)
        asm volatile("cp.async.wait_group 1;" ::: "memory");
        __syncthreads();

        // 4. refill buffer (2s+2)&3 (its reader, MMA plane 0 of s-1, is
        //    pre-barrier)
        if (2 * s + 2 < 2 * NSUPER) issue_w(2 * s + 2, sb, tid);

        const uint32_t* A =
            (const uint32_t*)(smem + S_A + (s & 1) * A_BYTES);

        // 5. MMA planes
#pragma unroll
        for (int h = 0; h < 2; h++) {
            if (h == 1) {
                // W half-chunk 2s+1 ready ((2s+2) may remain in flight)
                if (s < NSUPER - 1)
                    asm volatile("cp.async.wait_group 1;" ::: "memory");
                else
                    asm volatile("cp.async.wait_group 0;" ::: "memory");
                if (2 * s + 3 < 2 * NSUPER) issue_w(2 * s + 3, sb, tid);
            }
            const uint32_t* Ah = A + h * PLA;
            const uint32_t* Bh =
                (const uint32_t*)(smem + S_W + ((2 * s + h) & 3) * WH_BYTES);
            uint4 alo = *(const uint4*)(Ah + rlo * 16 + 4 * t);
            uint4 ahi = *(const uint4*)(Ah + rhi * 16 + 4 * t);
#pragma unroll
            for (int ntb = 0; ntb < 4; ntb++) {      // 2 n-tiles at a time
                const int n0 = wn * 64 + (ntb * 2) * 8 + g;
                uint4 bv0 = *(const uint4*)(Bh + n0 * 16 + 4 * t);
                uint4 bv1 = *(const uint4*)(Bh + (n0 + 8) * 16 + 4 * t);
                // kstep 0: x,y ; kstep 1: z,w
                mma16(acc[ntb * 2],     alo.x, ahi.x, alo.y, ahi.y,
                      bv0.x, bv0.y);
                mma16(acc[ntb * 2 + 1], alo.x, ahi.x, alo.y, ahi.y,
                      bv1.x, bv1.y);
                mma16(acc[ntb * 2],     alo.z, ahi.z, alo.w, ahi.w,
                      bv0.z, bv0.w);
                mma16(acc[ntb * 2 + 1], alo.z, ahi.z, alo.w, ahi.w,
                      bv1.z, bv1.w);
            }
        }

        // 6. user-tower epilogue: bias + relu -> fp16 global scratch
        if (s == NSUPER / 2 - 1) {
#pragma unroll
            for (int nt = 0; nt < 8; nt++) {
                const int c0 = wn * 64 + nt * 8 + 2 * t;
                float u0 = fmaxf(acc[nt][0] + ubS[c0],     0.f);
                float u1 = fmaxf(acc[nt][1] + ubS[c0 + 1], 0.f);
                float u2 = fmaxf(acc[nt][2] + ubS[c0],     0.f);
                float u3 = fmaxf(acc[nt][3] + ubS[c0 + 1], 0.f);
                const int cc = wn * 32 + nt * 4 + t;     // half2 column
                ulat_g[glo * 128 + cc] = __floats2half2_rn(u0, u1);
                ulat_g[ghi * 128 + cc] = __floats2half2_rn(u2, u3);
                acc[nt][0] = acc[nt][1] = acc[nt][2] = acc[nt][3] = 0.f;
            }
        }
    }

    // item-tower epilogue: bias+relu, product with user latent, row-reduce
    {
        float s0 = 0.f, s1 = 0.f;
#pragma unroll
        for (int nt = 0; nt < 8; nt++) {
            const int c0 = wn * 64 + nt * 8 + 2 * t;
            float v0 = fmaxf(acc[nt][0] + ibS[c0],     0.f);
            float v1 = fmaxf(acc[nt][1] + ibS[c0 + 1], 0.f);
            float v2 = fmaxf(acc[nt][2] + ibS[c0],     0.f);
            float v3 = fmaxf(acc[nt][3] + ibS[c0 + 1], 0.f);
            const int cc = wn * 32 + nt * 4 + t;
            float2 u01 = __half22float2(ulat_g[glo * 128 + cc]);
            float2 u23 = __half22float2(ulat_g[ghi * 128 + cc]);
            s0 = fmaf(u01.x, v0, fmaf(u01.y, v1, s0));
            s1 = fmaf(u23.x, v2, fmaf(u23.y, v3, s1));
        }
        s0 += __shfl_xor_sync(0xffffffffu, s0, 1);
        s0 += __shfl_xor_sync(0xffffffffu, s0, 2);
        s1 += __shfl_xor_sync(0xffffffffu, s1, 1);
        s1 += __shfl_xor_sync(0xffffffffu, s1, 2);
        if (t == 0) {
            atomicAdd(&part[rlo], s0);
            atomicAdd(&part[rhi], s1);
        }
    }
    __syncthreads();

    if (tid < TB) out[blockIdx.x * TB + tid] = part[tid];
}

// --------------------------- launch -----------------------------------------

extern "C" void kernel_launch(void* const* d_in, const int* in_sizes, int n_in,
                              void* d_out, int out_size) {
    const int* x      = (const int*)d_in[0];
    const float* ulut = (const float*)d_in[1];
    const float* ilut = (const float*)d_in[2];
    const float* uW   = (const float*)d_in[3];
    const float* ub   = (const float*)d_in[4];
    const float* iW   = (const float*)d_in[5];
    const float* ib   = (const float*)d_in[6];
    float* out        = (float*)d_out;

    prep_kernel<<<2 * 16 * LOUT * 16 / 256, 256>>>(uW, iW);

    cudaFuncSetAttribute(towers_kernel,
                         cudaFuncAttributeMaxDynamicSharedMemorySize, S_TOTAL);
    int grid = out_size / TB;   // 16384 / 64 = 256
    towers_kernel<<<grid, NTHREADS, S_TOTAL>>>(x, ulut, ilut, ub, ib, out);
}